// round 12
// baseline (speedup 1.0000x reference)
#include <cuda_runtime.h>
#include <math.h>

#define B_   16
#define C_   1024
#define BC_  (B_ * C_)
#define EPSf  1e-12f
#define TINYf 1e-9f
#define ROWS_ 8

#define BCC_    ((size_t)BC_ * (size_t)C_)
#define OFF_SL  ((size_t)0)
#define OFF_SU  ((size_t)BC_)
#define OFF_LC  ((size_t)(2 * BC_))
#define OFF_UC  ((size_t)(2 * BC_) + BCC_)
#define OFF_LB  ((size_t)(2 * BC_) + 2 * BCC_)
#define OFF_UB  ((size_t)(2 * BC_) + 2 * BCC_ + BC_)

typedef unsigned long long ull;

__device__ __forceinline__ float sqrt_apx(float x) {
    float r;
    asm("sqrt.approx.f32 %0, %1;" : "=f"(r) : "f"(x));
    return r;
}
__device__ __forceinline__ float rcp_apx(float x) {
    float r;
    asm("rcp.approx.f32 %0, %1;" : "=f"(r) : "f"(x));
    return r;
}
__device__ __forceinline__ ull pack2(float lo, float hi) {
    ull r;
    asm("mov.b64 %0, {%1, %2};" : "=l"(r) : "f"(lo), "f"(hi));
    return r;
}
__device__ __forceinline__ void unpack2(ull v, float& lo, float& hi) {
    asm("mov.b64 {%0, %1}, %2;" : "=f"(lo), "=f"(hi) : "l"(v));
}
__device__ __forceinline__ ull mul2(ull a, ull b) {
    ull r;
    asm("mul.rn.f32x2 %0, %1, %2;" : "=l"(r) : "l"(a), "l"(b));
    return r;
}
__device__ __forceinline__ ull add2(ull a, ull b) {
    ull r;
    asm("add.rn.f32x2 %0, %1, %2;" : "=l"(r) : "l"(a), "l"(b));
    return r;
}
__device__ __forceinline__ ull fma2(ull a, ull b, ull c) {
    ull r;
    asm("fma.rn.f32x2 %0, %1, %2, %3;" : "=l"(r) : "l"(a), "l"(b), "l"(c));
    return r;
}

// Single fused kernel: one block per 8 rows of one batch; inner arithmetic in
// packed f32x2 (2 cells per instruction).
__global__ __launch_bounds__(256, 6) void bs_kernel(
    const float* __restrict__ lower,
    const float* __restrict__ upper,
    float* __restrict__ out)
{
    const int row0 = blockIdx.x << 3;        // b*C + i0
    const int b    = row0 >> 10;
    const int i0   = row0 & (C_ - 1);
    const int tid  = threadIdx.x;
    const int j0   = tid << 2;

    const float* __restrict__ lrow = lower + (size_t)b * C_;
    const float* __restrict__ urow = upper + (size_t)b * C_;

    // j-chunk loads
    float4 lj = *reinterpret_cast<const float4*>(lrow + j0);
    float4 uj = *reinterpret_cast<const float4*>(urow + j0);
    const float* ljp = reinterpret_cast<const float*>(&lj);
    const float* ujp = reinterpret_cast<const float*>(&uj);

    // per-j exponentials (computed, not loaded)
    float Elj[4], Euj[4], Emj[4], wjv[4];
    float pEl = 0.f, pEu = 0.f, pEm = 0.f, pEmM = 0.f;
#pragma unroll
    for (int k = 0; k < 4; ++k) {
        float l = ljp[k], u = ujp[k];
        Elj[k] = __expf(l);
        Euj[k] = __expf(u);
        Emj[k] = sqrt_apx(Elj[k] * Euj[k]);   // exp((l+u)/2)
        wjv[k] = u - l;
        pEl  += Elj[k];
        pEu  += Euj[k];
        pEm  += Emj[k];
        pEmM  = fmaf(Emj[k], 0.5f * (l + u), pEmM);
    }

    // pack j-pairs for the f32x2 main loop
    ull nElj2[2], Euj2[2], Emj2[2], wj2[2], lj2[2];
#pragma unroll
    for (int p = 0; p < 2; ++p) {
        nElj2[p] = pack2(-Elj[2 * p], -Elj[2 * p + 1]);
        Euj2 [p] = pack2(Euj[2 * p],  Euj[2 * p + 1]);
        Emj2 [p] = pack2(Emj[2 * p],  Emj[2 * p + 1]);
        wj2  [p] = pack2(wjv[2 * p],  wjv[2 * p + 1]);
        lj2  [p] = pack2(ljp[2 * p],  ljp[2 * p + 1]);
    }

    __shared__ float sred[16][256];
    __shared__ float sres[16];
    __shared__ ull   rowk[ROWS_][5];    // pre-splatted loop constants
    __shared__ float rowc[ROWS_][6];    // finalize scalars

    // block-reduce the 4 batch sums (warp w reduces var w)
    sred[0][tid] = pEl;
    sred[1][tid] = pEu;
    sred[2][tid] = pEm;
    sred[3][tid] = pEmM;
    __syncthreads();
    {
        const int warp = tid >> 5;
        const int lane = tid & 31;
        if (warp < 4) {
            float s = 0.f;
#pragma unroll
            for (int jj = 0; jj < 8; ++jj) s += sred[warp][lane + 32 * jj];
#pragma unroll
            for (int m = 16; m > 0; m >>= 1) s += __shfl_xor_sync(0xffffffffu, s, m);
            if (lane == 0) sres[warp] = s;
        }
    }
    __syncthreads();

    // per-row constants (8 threads)
    if (tid < ROWS_) {
        const int r   = tid;
        const int row = row0 + r;
        const float l_i  = lrow[i0 + r];
        const float u_i  = urow[i0 + r];
        const float El_i = __expf(l_i);
        const float Eu_i = __expf(u_i);
        const float ElNi = __expf(-l_i);
        const float EuNi = __expf(-u_i);

        const float SumEl  = sres[0];
        const float SumEu  = sres[1];
        const float SumEm  = sres[2];
        const float SumEmM = sres[3];

        const float S_l = EuNi * (SumEl - El_i);
        const float S_u = ElNi * (SumEu - Eu_i);
        float g_l = __fdividef(1.0f, 1.0f + S_l);
        float g_u = __fdividef(1.0f, 1.0f + S_u);
        float dg  = S_u - S_l;
        float m_l = -g_u * g_u;
        float m_u = __fdividef(g_u - g_l, dg + EPSf);
        if (fabsf(dg) < TINYf) m_u = m_l;
        const float c_u = g_l - m_u * S_l;
        const float c_l = g_u - m_l * S_u;

        const float m_i  = 0.5f * (l_i + u_i);
        const float Em_i = sqrt_apx(El_i * Eu_i);   // exp(m_i)
        const float EmNi = sqrt_apx(ElNi * EuNi);   // exp(-m_i)
        const float Al   = EmNi * (SumEm - Em_i);
        const float Bl   = (1.0f + m_i) * Al - EmNi * (SumEmM - Em_i * m_i);

        out[OFF_SL + row] = fminf(fmaxf(g_u, 0.0f), 1.0f);
        out[OFF_SU + row] = fminf(fmaxf(g_l, 0.0f), 1.0f);
        out[OFF_LB + row] = m_l * Bl + c_l;

        const float wiE = (u_i - l_i) + EPSf;
        const float flr = m_l * EmNi;

        rowk[r][0] = pack2(ElNi, ElNi);
        rowk[r][1] = pack2(EuNi, EuNi);
        rowk[r][2] = pack2(wiE, wiE);
        rowk[r][3] = pack2(m_u, m_u);
        rowk[r][4] = pack2(flr, flr);

        rowc[r][0] = wiE;
        rowc[r][1] = m_u;
        rowc[r][2] = S_l;
        rowc[r][3] = c_u;
        rowc[r][4] = m_l * (-Al);                       // lower diag value
        rowc[r][5] = fmaf(Eu_i, ElNi, -(El_i * EuNi));  // num at diagonal (matches loop)
    }
    __syncthreads();

    // main loop: 8 rows, packed f32x2 arithmetic, fused stores
#pragma unroll
    for (int r = 0; r < ROWS_; ++r) {
        const ull ElN2 = rowk[r][0];
        const ull EuN2 = rowk[r][1];
        const ull wiE2 = rowk[r][2];
        const ull mur2 = rowk[r][3];
        const ull flr2 = rowk[r][4];
        ull aAu2 = 0ull, aAuL2 = 0ull;
        float4 ocu, ocl;
#pragma unroll
        for (int p = 0; p < 2; ++p) {
            ull eln = mul2(nElj2[p], EuN2);          // -exp(l_j - u_i) pair
            ull num = fma2(Euj2[p], ElN2, eln);      // exp(u_j-l_i) - exp(l_j-u_i)
            ull dn  = add2(wj2[p], wiE2);            // w_j + w_i + EPS
            float d0, d1;
            unpack2(dn, d0, d1);
            ull inv = pack2(rcp_apx(d0), rcp_apx(d1));
            ull au  = mul2(num, inv);
            aAu2  = add2(aAu2, au);
            aAuL2 = fma2(au, lj2[p], aAuL2);
            ull up = mul2(mur2, au);
            ull lp = mul2(flr2, Emj2[p]);
            if (p == 0) { unpack2(up, ocu.x, ocu.y); unpack2(lp, ocl.x, ocl.y); }
            else        { unpack2(up, ocu.z, ocu.w); unpack2(lp, ocl.z, ocl.w); }
        }
        const size_t base = (size_t)(row0 + r) * C_ + j0;
        *reinterpret_cast<float4*>(out + OFF_UC + base) = ocu;
        *reinterpret_cast<float4*>(out + OFF_LC + base) = ocl;
        float a0, a1;
        unpack2(aAu2, a0, a1);
        sred[2 * r][tid] = a0 + a1;
        unpack2(aAuL2, a0, a1);
        sred[2 * r + 1][tid] = a0 + a1;
    }
    __syncthreads();

    // transpose-reduce 16 partials: each warp reduces 2 variables
    {
        const int warp = tid >> 5;
        const int lane = tid & 31;
#pragma unroll
        for (int h = 0; h < 2; ++h) {
            const int v = warp + 8 * h;
            float s = 0.f;
#pragma unroll
            for (int jj = 0; jj < 8; ++jj) s += sred[v][lane + 32 * jj];
#pragma unroll
            for (int m = 16; m > 0; m >>= 1) s += __shfl_xor_sync(0xffffffffu, s, m);
            if (lane == 0) sres[v] = s;
        }
    }
    __syncthreads();

    // finalize: upper bias + diagonal coef entries (barrier orders overwrite)
    if (tid < ROWS_) {
        const int r   = tid;
        const int row = row0 + r;
        float Au  = sres[2 * r];
        float AuL = sres[2 * r + 1];

        const float l_i  = lrow[i0 + r];
        const float u_i  = urow[i0 + r];
        const float wiEr = rowc[r][0];
        const float m_u  = rowc[r][1];
        const float S_l  = rowc[r][2];
        const float c_u  = rowc[r][3];

        // subtract diagonal a_u exactly as the main loop computed it
        {
            float a_ud = rowc[r][5] * rcp_apx((u_i - l_i) + wiEr);
            Au  -= a_ud;
            AuL -= a_ud * l_i;
        }
        const float Bu = S_l - AuL + u_i * Au;
        out[OFF_UB + row] = m_u * Bu + c_u;

        const size_t dbase = (size_t)row * C_ + (size_t)(i0 + r);
        out[OFF_UC + dbase] = m_u * (-Au);
        out[OFF_LC + dbase] = rowc[r][4];
    }
}

extern "C" void kernel_launch(void* const* d_in, const int* in_sizes, int n_in,
                              void* d_out, int out_size) {
    const float* lower = (const float*)d_in[0];
    const float* upper = (const float*)d_in[1];
    float* out = (float*)d_out;
    bs_kernel<<<BC_ / ROWS_, 256>>>(lower, upper, out);
}